// round 5
// baseline (speedup 1.0000x reference)
#include <cuda_runtime.h>
#include <math.h>

#define N_ENT 4096
#define BATCH 4
#define NHID  3
#define ROWS_T (BATCH*N_ENT)     // 16384
#define RBLK_MAX 112

// dynamic smem layout for k_main:
//   [0, 65536)            sAdj: 2 stages x (4 rows x 2 chunks x 256 thr x 16B)
//   [65536, 65536+1792)   sRow: RBLK_MAX float4
//   [67328, 67328+14336)  sPart: 8 warps x RBLK_MAX x 4 floats
#define SADJ_BYTES   65536
#define SROW_OFF     SADJ_BYTES
#define SPART_OFF    (SROW_OFF + RBLK_MAX*16)
#define SMEM_MAIN    (SPART_OFF + 8*RBLK_MAX*4*4)   // 81664 B

// ---------------- device scratch ----------------
__device__ float4  g_tabH[N_ENT];        // h0, h1, h2, dst
__device__ float   g_src[N_ENT];
__device__ unsigned g_dmax_u = 0;        // encoded float max (idempotent)
__device__ float4  g_part[2*ROWS_T];     // per column-half partial (den,n0,n1,n2)
__device__ float   g_x[ROWS_T*NHID];

__device__ __forceinline__ unsigned fenc(float f) {
    unsigned u = __float_as_uint(f);
    return (u & 0x80000000u) ? ~u : (u | 0x80000000u);
}
__device__ __forceinline__ float fdec(unsigned e) {
    return (e & 0x80000000u) ? __uint_as_float(e & 0x7fffffffu)
                             : __uint_as_float(~e);
}
__device__ __forceinline__ void cpa16(unsigned s, const void* g) {
    asm volatile("cp.async.cg.shared.global [%0], [%1], 16;" :: "r"(s), "l"(g));
}

// ---------------- K1: h = emb@W, src/dst per node, atomic dstmax ----------
__global__ void k_node(const float* __restrict__ emb,
                       const float* __restrict__ W,
                       const float* __restrict__ a) {
    __shared__ float sW[192];
    __shared__ float sa[6];
    __shared__ float sm[256];
    int t = threadIdx.x;
    if (t < 192) sW[t] = W[t];
    if (t < 6)   sa[t] = a[t];
    __syncthreads();

    int i = blockIdx.x * blockDim.x + t;
    const float4* ev = (const float4*)(emb + (size_t)i * 64);
    float h0 = 0.f, h1 = 0.f, h2 = 0.f;
#pragma unroll
    for (int k4 = 0; k4 < 16; k4++) {
        float4 e = ev[k4];
        int k = k4 * 4;
        h0 += e.x*sW[k*3+0] + e.y*sW[k*3+3] + e.z*sW[k*3+6] + e.w*sW[k*3+9];
        h1 += e.x*sW[k*3+1] + e.y*sW[k*3+4] + e.z*sW[k*3+7] + e.w*sW[k*3+10];
        h2 += e.x*sW[k*3+2] + e.y*sW[k*3+5] + e.z*sW[k*3+8] + e.w*sW[k*3+11];
    }
    float src = h0*sa[0] + h1*sa[1] + h2*sa[2];
    float dst = h0*sa[3] + h1*sa[4] + h2*sa[5];
    g_tabH[i] = make_float4(h0, h1, h2, dst);
    g_src[i]  = src;

    sm[t] = dst;
    __syncthreads();
    for (int s = 128; s > 0; s >>= 1) {
        if (t < s) sm[t] = fmaxf(sm[t], sm[t+s]);
        __syncthreads();
    }
    if (t == 0) atomicMax(&g_dmax_u, fenc(sm[0]));
}

// ---------------- K2: main pass over adj — cp.async pipelined warps -------
__global__ void __launch_bounds__(256, 2) k_main(const int* __restrict__ adj) {
    extern __shared__ char dsm[];
    int4*   sAdj  = (int4*)dsm;
    float4* sRow  = (float4*)(dsm + SROW_OFF);
    float*  sPart = (float*)(dsm + SPART_OFF);
    unsigned sb = (unsigned)__cvta_generic_to_shared(dsm);

    int t = threadIdx.x, w = t >> 5, lane = t & 31;
    int pair = blockIdx.x >> 1, ch = blockIdx.x & 1;
    int j0 = ch * 2048 + w * 256 + lane * 8;

    float dm = fdec(g_dmax_u);

    // per-lane column tables (register-resident)
    float p[8], q[8], h0[8], h1[8], h2[8];
#pragma unroll
    for (int k = 0; k < 8; k++) {
        float4 H = g_tabH[j0 + k];
        h0[k] = H.x; h1[k] = H.y; h2[k] = H.z;
        float d = H.w - dm;
        p[k] = expf(d);
        q[k] = expf(0.2f * d);
    }

    int pairs = gridDim.x >> 1;
    int rblk = (((ROWS_T + pairs - 1) / pairs) + 3) & ~3;
    if (rblk > RBLK_MAX) rblk = RBLK_MAX;
    int r_begin = pair * rblk;
    int iters = rblk >> 2;

    // per-row constants u, v, w0
    for (int r = t; r < rblk; r += 256) {
        int row = min(r_begin + r, ROWS_T - 1);
        float src = g_src[row & (N_ENT - 1)];
        float z  = src + dm;
        float lz = fmaxf(z, 0.2f * z);
        float m  = fmaxf(lz, 9e-15f);
        sRow[r] = make_float4(expf(z - m), expf(0.2f*z - m),
                              expf(9e-15f - m), 0.f);
    }
    __syncthreads();

    // tile issue: 4 rows x 2 x 16B per thread into stage slot
    auto issue_tile = [&](int it, int stage) {
        int row0 = r_begin + it * 4;
#pragma unroll
        for (int r = 0; r < 4; r++) {
            int rr = min(row0 + r, ROWS_T - 1);
            const int* gp = adj + (((size_t)rr) << 12) + j0;
            unsigned a0 = sb + (unsigned)(((stage*8 + r*2) * 256 + t) << 4);
            cpa16(a0, gp);
            cpa16(a0 + (256u << 4), gp + 4);
        }
        asm volatile("cp.async.commit_group;" ::: "memory");
    };

    issue_tile(0, 0);
    issue_tile(1, 1);

    for (int it = 0; it < iters; it++) {
        int stage = it & 1;
        asm volatile("cp.async.wait_group 1;" ::: "memory");

        float v[16];
#pragma unroll
        for (int r = 0; r < 4; r++) {
            float4 rc = sRow[it*4 + r];            // u, v, w0 (broadcast)
            int idx = (stage*8 + r*2) * 256 + t;
            int4 A = sAdj[idx];
            int4 B = sAdj[idx + 256];
            int va[8];
            *(int4*)&va[0] = A;
            *(int4*)&va[4] = B;
            float a0 = 0.f, a1 = 0.f, a2 = 0.f, a3 = 0.f;
#pragma unroll
            for (int k = 0; k < 8; k++) {
                float we = fmaxf(rc.x * p[k], rc.y * q[k]);
                float c  = (va[k] > 0) ? we : rc.z;
                a0 += c;
                a1 += c * h0[k];
                a2 += c * h1[k];
                a3 += c * h2[k];
            }
            v[r*4+0] = a0; v[r*4+1] = a1; v[r*4+2] = a2; v[r*4+3] = a3;
        }

        // butterfly transpose-reduce: lane i (i<16) ends with warp-total of v[i]
#pragma unroll
        for (int d = 8; d >= 1; d >>= 1) {
            int bit = (lane & d) ? 1 : 0;
#pragma unroll
            for (int k = 0; k < d; k++) {
                float snd = bit ? v[k] : v[k+d];
                float tmp = __shfl_xor_sync(0xffffffffu, snd, d);
                v[k] = (bit ? v[k+d] : v[k]) + tmp;
            }
        }
        v[0] += __shfl_xor_sync(0xffffffffu, v[0], 16);

        if (lane < 16)
            sPart[w * (RBLK_MAX*4) + it * 16 + lane] = v[0];

        issue_tile(it + 2, stage);
    }

    asm volatile("cp.async.wait_group 0;" ::: "memory");
    __syncthreads();

    // CTA epilogue: combine 8 warp slabs -> per-row partial float4
    for (int r = t; r < rblk; r += 256) {
        int row = r_begin + r;
        if (row >= ROWS_T) break;
        float den = 0.f, n0 = 0.f, n1 = 0.f, n2 = 0.f;
#pragma unroll
        for (int ww = 0; ww < 8; ww++) {
            const float* sp = &sPart[ww * (RBLK_MAX*4) + r * 4];
            den += sp[0]; n0 += sp[1]; n1 += sp[2]; n2 += sp[3];
        }
        g_part[(size_t)ch * ROWS_T + row] = make_float4(den, n0, n1, n2);
    }
}

// ---------------- K3: combine halves, ELU, build x; init out=bias --------
__global__ void k_x(const float* __restrict__ bias, float* __restrict__ out) {
    int idx = blockIdx.x * blockDim.x + threadIdx.x;   // 16384
    if (idx < BATCH*100) out[idx] = bias[idx % 100];
    float4 A = g_part[idx];
    float4 B = g_part[ROWS_T + idx];
    float inv = 1.0f / (A.x + B.x);
    float x0 = (A.y + B.y) * inv;
    float x1 = (A.z + B.z) * inv;
    float x2 = (A.w + B.w) * inv;
    x0 = (x0 > 0.f) ? x0 : (expf(x0) - 1.f);
    x1 = (x1 > 0.f) ? x1 : (expf(x1) - 1.f);
    x2 = (x2 > 0.f) ? x2 : (expf(x2) - 1.f);
    float* xp = g_x + (size_t)idx * NHID;
    xp[0] = x0; xp[1] = x1; xp[2] = x2;
}

// ---------------- K4: out += x @ fc1_w.T  (split-K, atomic combine) ------
__global__ void k_fc(const float* __restrict__ w, float* __restrict__ out) {
    int o  = blockIdx.x;          // 0..99
    int kc = blockIdx.y;          // 0..7
    int t  = threadIdx.x;         // 128
    int wp = t >> 5, lane = t & 31;
    const float4* wr = (const float4*)(w + (size_t)o * (N_ENT*NHID)) + kc*384;
    const float4* xv = (const float4*)g_x + kc*384;
    float a0 = 0.f, a1 = 0.f, a2 = 0.f, a3 = 0.f;
#pragma unroll
    for (int i = 0; i < 3; i++) {
        int k = i*128 + t;
        float4 wv = __ldg(wr + k);
        float4 xa = xv[k];
        float4 xb = xv[3072 + k];
        float4 xc = xv[6144 + k];
        float4 xd = xv[9216 + k];
        a0 += wv.x*xa.x + wv.y*xa.y + wv.z*xa.z + wv.w*xa.w;
        a1 += wv.x*xb.x + wv.y*xb.y + wv.z*xb.z + wv.w*xb.w;
        a2 += wv.x*xc.x + wv.y*xc.y + wv.z*xc.z + wv.w*xc.w;
        a3 += wv.x*xd.x + wv.y*xd.y + wv.z*xd.z + wv.w*xd.w;
    }
#pragma unroll
    for (int off = 16; off; off >>= 1) {
        a0 += __shfl_xor_sync(0xffffffffu, a0, off);
        a1 += __shfl_xor_sync(0xffffffffu, a1, off);
        a2 += __shfl_xor_sync(0xffffffffu, a2, off);
        a3 += __shfl_xor_sync(0xffffffffu, a3, off);
    }
    __shared__ float s4[4][4];
    if (lane == 0) {
        s4[0][wp] = a0; s4[1][wp] = a1; s4[2][wp] = a2; s4[3][wp] = a3;
    }
    __syncthreads();
    if (t < 4) {
        float r = s4[t][0] + s4[t][1] + s4[t][2] + s4[t][3];
        atomicAdd(&out[t*100 + o], r);
    }
}

// ---------------- launcher ----------------
extern "C" void kernel_launch(void* const* d_in, const int* in_sizes, int n_in,
                              void* d_out, int out_size) {
    const int*   adj  = (const int*)  d_in[0];
    const float* emb  = (const float*)d_in[1];
    const float* W    = (const float*)d_in[2];
    const float* a    = (const float*)d_in[3];
    const float* fc1w = (const float*)d_in[4];
    const float* fc1b = (const float*)d_in[5];
    float* out = (float*)d_out;

    static_assert(SMEM_MAIN <= 112*1024, "smem budget");
    cudaFuncSetAttribute(k_main, cudaFuncAttributeMaxDynamicSharedMemorySize,
                         SMEM_MAIN);

    k_node<<<N_ENT/256, 256>>>(emb, W, a);

    int sms = 148;
    int dev = 0;
    if (cudaGetDevice(&dev) == cudaSuccess) {
        int v = 0;
        if (cudaDeviceGetAttribute(&v, cudaDevAttrMultiProcessorCount, dev) == cudaSuccess && v > 0)
            sms = v;
    }
    k_main<<<2*sms, 256, SMEM_MAIN>>>(adj);

    k_x <<<ROWS_T/256, 256>>>(fc1b, out);
    k_fc<<<dim3(100, 8), 128>>>(fc1w, out);
}

// round 6
// speedup vs baseline: 1.4771x; 1.4771x over previous
#include <cuda_runtime.h>
#include <math.h>

#define N_ENT 4096
#define BATCH 4
#define NHID  3
#define ROWS_T (BATCH*N_ENT)     // 16384
#define RBLK_MAX 160

// ---------------- device scratch ----------------
__device__ float4  g_tabH[N_ENT];        // h0, h1, h2, dst
__device__ float   g_src[N_ENT];
__device__ unsigned g_dmax_u = 0;        // encoded float max (idempotent)
__device__ float4  g_part[4*ROWS_T];     // per column-quarter partials
__device__ float   g_x[ROWS_T*NHID];

__device__ __forceinline__ unsigned fenc(float f) {
    unsigned u = __float_as_uint(f);
    return (u & 0x80000000u) ? ~u : (u | 0x80000000u);
}
__device__ __forceinline__ float fdec(unsigned e) {
    return (e & 0x80000000u) ? __uint_as_float(e & 0x7fffffffu)
                             : __uint_as_float(~e);
}

// ---------------- K1: h = emb@W, src/dst per node, atomic dstmax ----------
__global__ void k_node(const float* __restrict__ emb,
                       const float* __restrict__ W,
                       const float* __restrict__ a) {
    __shared__ float sW[192];
    __shared__ float sa[6];
    __shared__ float sm[256];
    int t = threadIdx.x;
    if (t < 192) sW[t] = W[t];
    if (t < 6)   sa[t] = a[t];
    __syncthreads();

    int i = blockIdx.x * blockDim.x + t;
    const float4* ev = (const float4*)(emb + (size_t)i * 64);
    float h0 = 0.f, h1 = 0.f, h2 = 0.f;
#pragma unroll
    for (int k4 = 0; k4 < 16; k4++) {
        float4 e = ev[k4];
        int k = k4 * 4;
        h0 += e.x*sW[k*3+0] + e.y*sW[k*3+3] + e.z*sW[k*3+6] + e.w*sW[k*3+9];
        h1 += e.x*sW[k*3+1] + e.y*sW[k*3+4] + e.z*sW[k*3+7] + e.w*sW[k*3+10];
        h2 += e.x*sW[k*3+2] + e.y*sW[k*3+5] + e.z*sW[k*3+8] + e.w*sW[k*3+11];
    }
    float src = h0*sa[0] + h1*sa[1] + h2*sa[2];
    float dst = h0*sa[3] + h1*sa[4] + h2*sa[5];
    g_tabH[i] = make_float4(h0, h1, h2, dst);
    g_src[i]  = src;

    sm[t] = dst;
    __syncthreads();
    for (int s = 128; s > 0; s >>= 1) {
        if (t < s) sm[t] = fmaxf(sm[t], sm[t+s]);
        __syncthreads();
    }
    if (t == 0) atomicMax(&g_dmax_u, fenc(sm[0]));
}

// ---------------- K2: main pass over adj — barrier-free warps, occ=3 -----
// Grid = 4*rowgroups. quarter = bid&3 owns columns [q*1024, q*1024+1024);
// rowgroup = bid>>2 owns a row chunk. Warp w owns 128 cols; lane owns 4
// (tables register-resident). Per-row softmax constants in smem. 4 rows/iter,
// butterfly transpose-reduce, per-warp slab, epilogue writes float4 partial.
__global__ void __launch_bounds__(256, 3) k_main(const int* __restrict__ adj) {
    int t = threadIdx.x, w = t >> 5, lane = t & 31;
    int rg = blockIdx.x >> 2, qt = blockIdx.x & 3;
    int j0 = qt * 1024 + w * 128 + lane * 4;

    float dm = fdec(g_dmax_u);

    // per-lane column tables (register-resident)
    float p[4], q[4], h0[4], h1[4], h2[4];
#pragma unroll
    for (int k = 0; k < 4; k++) {
        float4 H = g_tabH[j0 + k];
        h0[k] = H.x; h1[k] = H.y; h2[k] = H.z;
        float d = H.w - dm;
        p[k] = expf(d);
        q[k] = expf(0.2f * d);
    }

    int rowgroups = gridDim.x >> 2;
    int rblk = (((ROWS_T + rowgroups - 1) / rowgroups) + 3) & ~3;
    if (rblk > RBLK_MAX) rblk = RBLK_MAX;
    int r_begin = rg * rblk;
    int iters = rblk >> 2;

    // per-row constants u, v, w0
    __shared__ float4 sRow[RBLK_MAX];
    for (int r = t; r < rblk; r += 256) {
        int row = min(r_begin + r, ROWS_T - 1);
        float src = g_src[row & (N_ENT - 1)];
        float z  = src + dm;
        float lz = fmaxf(z, 0.2f * z);
        float m  = fmaxf(lz, 9e-15f);
        sRow[r] = make_float4(expf(z - m), expf(0.2f*z - m),
                              expf(9e-15f - m), 0.f);
    }
    __syncthreads();

    __shared__ float sPart[8][RBLK_MAX * 4];   // 20 KB

    for (int it = 0; it < iters; it++) {
        int row0 = r_begin + it * 4;

        int4 av[4];
#pragma unroll
        for (int r = 0; r < 4; r++) {
            int rr = min(row0 + r, ROWS_T - 1);
            av[r] = __ldg((const int4*)adj + (((size_t)rr) << 10) + (j0 >> 2));
        }

        float v[16];
#pragma unroll
        for (int r = 0; r < 4; r++) {
            float4 rc = sRow[it*4 + r];     // u, v, w0 (broadcast LDS.128)
            int va[4];
            *(int4*)&va[0] = av[r];
            float a0 = 0.f, a1 = 0.f, a2 = 0.f, a3 = 0.f;
#pragma unroll
            for (int k = 0; k < 4; k++) {
                float we = fmaxf(rc.x * p[k], rc.y * q[k]);
                float c  = (va[k] > 0) ? we : rc.z;
                a0 += c;
                a1 += c * h0[k];
                a2 += c * h1[k];
                a3 += c * h2[k];
            }
            v[r*4+0] = a0; v[r*4+1] = a1; v[r*4+2] = a2; v[r*4+3] = a3;
        }

        // butterfly transpose-reduce: lane i (i<16) ends with warp-total of v[i]
#pragma unroll
        for (int d = 8; d >= 1; d >>= 1) {
            int bit = (lane & d) ? 1 : 0;
#pragma unroll
            for (int k = 0; k < d; k++) {
                float snd = bit ? v[k] : v[k+d];
                float tmp = __shfl_xor_sync(0xffffffffu, snd, d);
                v[k] = (bit ? v[k+d] : v[k]) + tmp;
            }
        }
        v[0] += __shfl_xor_sync(0xffffffffu, v[0], 16);

        if (lane < 16)
            sPart[w][it * 16 + lane] = v[0];
    }

    __syncthreads();

    // epilogue: combine 8 warp slabs -> per-row partial float4
    for (int r = t; r < rblk; r += 256) {
        int row = r_begin + r;
        if (row >= ROWS_T) break;
        float den = 0.f, n0 = 0.f, n1 = 0.f, n2 = 0.f;
#pragma unroll
        for (int ww = 0; ww < 8; ww++) {
            const float* sp = &sPart[ww][r * 4];
            den += sp[0]; n0 += sp[1]; n1 += sp[2]; n2 += sp[3];
        }
        g_part[(size_t)qt * ROWS_T + row] = make_float4(den, n0, n1, n2);
    }
}

// ---------------- K3: combine quarters, ELU, build x; init out=bias ------
__global__ void k_x(const float* __restrict__ bias, float* __restrict__ out) {
    int idx = blockIdx.x * blockDim.x + threadIdx.x;   // 16384
    if (idx < BATCH*100) out[idx] = bias[idx % 100];
    float4 A = g_part[idx];
    float4 B = g_part[ROWS_T + idx];
    float4 C = g_part[2*ROWS_T + idx];
    float4 D = g_part[3*ROWS_T + idx];
    float inv = 1.0f / (A.x + B.x + C.x + D.x);
    float x0 = (A.y + B.y + C.y + D.y) * inv;
    float x1 = (A.z + B.z + C.z + D.z) * inv;
    float x2 = (A.w + B.w + C.w + D.w) * inv;
    x0 = (x0 > 0.f) ? x0 : (expf(x0) - 1.f);
    x1 = (x1 > 0.f) ? x1 : (expf(x1) - 1.f);
    x2 = (x2 > 0.f) ? x2 : (expf(x2) - 1.f);
    float* xp = g_x + (size_t)idx * NHID;
    xp[0] = x0; xp[1] = x1; xp[2] = x2;
}

// ---------------- K4: out += x @ fc1_w.T  (split-K 12, high MLP) ---------
__global__ void k_fc(const float* __restrict__ w, float* __restrict__ out) {
    int o  = blockIdx.x;          // 0..99
    int kc = blockIdx.y;          // 0..11
    int t  = threadIdx.x;         // 128
    int wp = t >> 5, lane = t & 31;
    const int K4 = (N_ENT*NHID)/4;            // 3072 float4 per batch
    const float4* wr = (const float4*)(w + (size_t)o * (N_ENT*NHID));
    const float4* xv = (const float4*)g_x;
    int k0 = kc * 256 + t;                    // two k's: k0, k0+128

    // 10 independent loads in flight
    float4 w0 = __ldg(wr + k0);
    float4 w1 = __ldg(wr + k0 + 128);
    float4 xa0 = xv[k0],          xa1 = xv[k0 + 128];
    float4 xb0 = xv[K4 + k0],     xb1 = xv[K4 + k0 + 128];
    float4 xc0 = xv[2*K4 + k0],   xc1 = xv[2*K4 + k0 + 128];
    float4 xd0 = xv[3*K4 + k0],   xd1 = xv[3*K4 + k0 + 128];

    float a0 = w0.x*xa0.x + w0.y*xa0.y + w0.z*xa0.z + w0.w*xa0.w
             + w1.x*xa1.x + w1.y*xa1.y + w1.z*xa1.z + w1.w*xa1.w;
    float a1 = w0.x*xb0.x + w0.y*xb0.y + w0.z*xb0.z + w0.w*xb0.w
             + w1.x*xb1.x + w1.y*xb1.y + w1.z*xb1.z + w1.w*xb1.w;
    float a2 = w0.x*xc0.x + w0.y*xc0.y + w0.z*xc0.z + w0.w*xc0.w
             + w1.x*xc1.x + w1.y*xc1.y + w1.z*xc1.z + w1.w*xc1.w;
    float a3 = w0.x*xd0.x + w0.y*xd0.y + w0.z*xd0.z + w0.w*xd0.w
             + w1.x*xd1.x + w1.y*xd1.y + w1.z*xd1.z + w1.w*xd1.w;

#pragma unroll
    for (int off = 16; off; off >>= 1) {
        a0 += __shfl_xor_sync(0xffffffffu, a0, off);
        a1 += __shfl_xor_sync(0xffffffffu, a1, off);
        a2 += __shfl_xor_sync(0xffffffffu, a2, off);
        a3 += __shfl_xor_sync(0xffffffffu, a3, off);
    }
    __shared__ float s4[4][4];
    if (lane == 0) {
        s4[0][wp] = a0; s4[1][wp] = a1; s4[2][wp] = a2; s4[3][wp] = a3;
    }
    __syncthreads();
    if (t < 4) {
        float r = s4[t][0] + s4[t][1] + s4[t][2] + s4[t][3];
        atomicAdd(&out[t*100 + o], r);
    }
}

// ---------------- launcher ----------------
extern "C" void kernel_launch(void* const* d_in, const int* in_sizes, int n_in,
                              void* d_out, int out_size) {
    const int*   adj  = (const int*)  d_in[0];
    const float* emb  = (const float*)d_in[1];
    const float* W    = (const float*)d_in[2];
    const float* a    = (const float*)d_in[3];
    const float* fc1w = (const float*)d_in[4];
    const float* fc1b = (const float*)d_in[5];
    float* out = (float*)d_out;

    k_node<<<N_ENT/256, 256>>>(emb, W, a);

    int sms = 148;
    int dev = 0;
    if (cudaGetDevice(&dev) == cudaSuccess) {
        int v = 0;
        if (cudaDeviceGetAttribute(&v, cudaDevAttrMultiProcessorCount, dev) == cudaSuccess && v > 0)
            sms = v;
    }
    int rowgroups = (3 * sms) / 4;           // 4 CTAs (column quarters) per group
    k_main<<<4 * rowgroups, 256>>>(adj);

    k_x <<<ROWS_T/256, 256>>>(fc1b, out);
    k_fc<<<dim3(100, 12), 128>>>(fc1w, out);
}

// round 7
// speedup vs baseline: 1.4778x; 1.0005x over previous
#include <cuda_runtime.h>
#include <math.h>

#define N_ENT 4096
#define BATCH 4
#define NHID  3
#define ROWS_T (BATCH*N_ENT)     // 16384
#define RBLK_MAX 112             // rows per block (pad to 8)
#define TILE_ROWS 8
#define TILE_BYTES 65536         // 8 rows x 2048 ints x 4B
#define NTHR 512

// dynamic smem layout for k_main:
//   [0, 131072)   sAdj: 2 stages x 64KB
//   [131072, +1792)  sRow: RBLK_MAX float4
//   [132864, +28672) sPart: 16 warps x RBLK_MAX x 4 floats
//   [161536, +64)    mbarriers (2 x 8B, padded)
#define SROW_OFF   131072
#define SPART_OFF  (SROW_OFF + RBLK_MAX*16)
#define SMBAR_OFF  (SPART_OFF + 16*RBLK_MAX*4*4)
#define SMEM_MAIN  (SMBAR_OFF + 64)

// ---------------- device scratch ----------------
__device__ float4  g_tabH[N_ENT];        // h0, h1, h2, dst
__device__ float   g_src[N_ENT];
__device__ unsigned g_dmax_u = 0;        // encoded float max (idempotent)
__device__ float4  g_part[2*ROWS_T];     // per column-half partials
__device__ float   g_x[ROWS_T*NHID];

__device__ __forceinline__ unsigned fenc(float f) {
    unsigned u = __float_as_uint(f);
    return (u & 0x80000000u) ? ~u : (u | 0x80000000u);
}
__device__ __forceinline__ float fdec(unsigned e) {
    return (e & 0x80000000u) ? __uint_as_float(e & 0x7fffffffu)
                             : __uint_as_float(~e);
}
__device__ __forceinline__ void mbar_init(unsigned m, unsigned cnt) {
    asm volatile("mbarrier.init.shared.b64 [%0], %1;" :: "r"(m), "r"(cnt) : "memory");
}
__device__ __forceinline__ void mbar_expect_tx(unsigned m, unsigned bytes) {
    asm volatile("mbarrier.arrive.expect_tx.shared.b64 _, [%0], %1;"
                 :: "r"(m), "r"(bytes) : "memory");
}
__device__ __forceinline__ void mbar_wait(unsigned m, unsigned phase) {
    asm volatile(
        "{\n\t.reg .pred P;\n"
        "W_%=:\n\t"
        "mbarrier.try_wait.parity.acquire.cta.shared::cta.b64 P, [%0], %1, 0x989680;\n\t"
        "@!P bra W_%=;\n\t}"
        :: "r"(m), "r"(phase) : "memory");
}
__device__ __forceinline__ void bulk_cp(unsigned dst, const void* src,
                                        unsigned bytes, unsigned m) {
    asm volatile(
        "cp.async.bulk.shared::cta.global.mbarrier::complete_tx::bytes "
        "[%0], [%1], %2, [%3];"
        :: "r"(dst), "l"(src), "r"(bytes), "r"(m) : "memory");
}

// ---------------- K1: h = emb@W, src/dst per node, atomic dstmax ----------
__global__ void k_node(const float* __restrict__ emb,
                       const float* __restrict__ W,
                       const float* __restrict__ a) {
    __shared__ float sW[192];
    __shared__ float sa[6];
    __shared__ float sm[256];
    int t = threadIdx.x;
    if (t < 192) sW[t] = W[t];
    if (t < 6)   sa[t] = a[t];
    __syncthreads();

    int i = blockIdx.x * blockDim.x + t;
    const float4* ev = (const float4*)(emb + (size_t)i * 64);
    float h0 = 0.f, h1 = 0.f, h2 = 0.f;
#pragma unroll
    for (int k4 = 0; k4 < 16; k4++) {
        float4 e = ev[k4];
        int k = k4 * 4;
        h0 += e.x*sW[k*3+0] + e.y*sW[k*3+3] + e.z*sW[k*3+6] + e.w*sW[k*3+9];
        h1 += e.x*sW[k*3+1] + e.y*sW[k*3+4] + e.z*sW[k*3+7] + e.w*sW[k*3+10];
        h2 += e.x*sW[k*3+2] + e.y*sW[k*3+5] + e.z*sW[k*3+8] + e.w*sW[k*3+11];
    }
    float src = h0*sa[0] + h1*sa[1] + h2*sa[2];
    float dst = h0*sa[3] + h1*sa[4] + h2*sa[5];
    g_tabH[i] = make_float4(h0, h1, h2, dst);
    g_src[i]  = src;

    sm[t] = dst;
    __syncthreads();
    for (int s = 128; s > 0; s >>= 1) {
        if (t < s) sm[t] = fmaxf(sm[t], sm[t+s]);
        __syncthreads();
    }
    if (t == 0) atomicMax(&g_dmax_u, fenc(sm[0]));
}

// ---------------- K2: main pass — cp.async.bulk double-buffered ----------
// Grid = 2*SMs. ch = bid&1 owns columns [ch*2048, ch*2048+2048); rg = bid>>1
// owns a row chunk. One CTA/SM, 512 threads. Producer (t0) streams 8-row x
// 8KB tiles via bulk copies into 2 smem stages; consumers (16 warps, lane
// owns 4 cols, tables in regs) compute + butterfly transpose-reduce.
__global__ void __launch_bounds__(NTHR, 1) k_main(const int* __restrict__ adj) {
    extern __shared__ char dsm[];
    float4* sRow  = (float4*)(dsm + SROW_OFF);
    float*  sPart = (float*)(dsm + SPART_OFF);
    unsigned sb   = (unsigned)__cvta_generic_to_shared(dsm);
    unsigned mbar0 = sb + SMBAR_OFF;
    unsigned mbar1 = sb + SMBAR_OFF + 16;

    int t = threadIdx.x, w = t >> 5, lane = t & 31;
    int rg = blockIdx.x >> 1, ch = blockIdx.x & 1;
    int j0 = ch * 2048 + w * 128 + lane * 4;

    float dm = fdec(g_dmax_u);

    // per-lane column tables (register-resident)
    float p[4], q[4], h0[4], h1[4], h2[4];
#pragma unroll
    for (int k = 0; k < 4; k++) {
        float4 H = g_tabH[j0 + k];
        h0[k] = H.x; h1[k] = H.y; h2[k] = H.z;
        float d = H.w - dm;
        p[k] = expf(d);
        q[k] = expf(0.2f * d);
    }

    int rowgroups = gridDim.x >> 1;
    int rblk = (((ROWS_T + rowgroups - 1) / rowgroups) + 7) & ~7;
    if (rblk > RBLK_MAX) rblk = RBLK_MAX;
    int r_begin = rg * rblk;
    int iters = rblk >> 3;            // 8 rows per tile

    // per-row constants u, v, w0
    for (int r = t; r < rblk; r += NTHR) {
        int row = min(r_begin + r, ROWS_T - 1);
        float src = g_src[row & (N_ENT - 1)];
        float z  = src + dm;
        float lz = fmaxf(z, 0.2f * z);
        float m  = fmaxf(lz, 9e-15f);
        sRow[r] = make_float4(expf(z - m), expf(0.2f*z - m),
                              expf(9e-15f - m), 0.f);
    }

    if (t == 0) {
        mbar_init(mbar0, 1);
        mbar_init(mbar1, 1);
    }
    __syncthreads();
    asm volatile("fence.proxy.async.shared::cta;" ::: "memory");

    // producer: issue 8 row-chunks (8KB each) for tile 'it' into 'stage'
    auto issue = [&](int it, int stage) {
        unsigned m = stage ? mbar1 : mbar0;
        mbar_expect_tx(m, TILE_BYTES);
        int row0 = r_begin + it * TILE_ROWS;
#pragma unroll
        for (int r = 0; r < TILE_ROWS; r++) {
            int rr = min(row0 + r, ROWS_T - 1);
            const int* gp = adj + (((size_t)rr) << 12) + ch * 2048;
            bulk_cp(sb + (unsigned)(stage*TILE_BYTES + r*8192), gp, 8192, m);
        }
    };

    if (t == 0) { issue(0, 0); issue(1, 1); }

    for (int it = 0; it < iters; it++) {
        int stage = it & 1;
        mbar_wait(stage ? mbar1 : mbar0, (it >> 1) & 1);

        const int4* sT = (const int4*)(dsm + stage * TILE_BYTES);
        int base = w * 32 + lane;     // int4 index of this lane's 4 cols

#pragma unroll
        for (int half = 0; half < 2; half++) {
            int4 av[4];
#pragma unroll
            for (int r = 0; r < 4; r++)
                av[r] = sT[(half*4 + r) * 512 + base];

            float v[16];
#pragma unroll
            for (int r = 0; r < 4; r++) {
                float4 rc = sRow[it*8 + half*4 + r];   // u, v, w0
                int va[4];
                *(int4*)&va[0] = av[r];
                float a0 = 0.f, a1 = 0.f, a2 = 0.f, a3 = 0.f;
#pragma unroll
                for (int k = 0; k < 4; k++) {
                    float we = fmaxf(rc.x * p[k], rc.y * q[k]);
                    float c  = (va[k] > 0) ? we : rc.z;
                    a0 += c;
                    a1 += c * h0[k];
                    a2 += c * h1[k];
                    a3 += c * h2[k];
                }
                v[r*4+0] = a0; v[r*4+1] = a1; v[r*4+2] = a2; v[r*4+3] = a3;
            }

            // butterfly transpose-reduce: lane i (i<16) = warp-total of v[i]
#pragma unroll
            for (int d = 8; d >= 1; d >>= 1) {
                int bit = (lane & d) ? 1 : 0;
#pragma unroll
                for (int k = 0; k < d; k++) {
                    float snd = bit ? v[k] : v[k+d];
                    float tmp = __shfl_xor_sync(0xffffffffu, snd, d);
                    v[k] = (bit ? v[k+d] : v[k]) + tmp;
                }
            }
            v[0] += __shfl_xor_sync(0xffffffffu, v[0], 16);

            if (lane < 16)
                sPart[w * (RBLK_MAX*4) + it*32 + half*16 + lane] = v[0];
        }

        __syncthreads();                      // stage fully consumed
        if (t == 0 && it + 2 < iters) issue(it + 2, stage);
    }

    // epilogue: combine 16 warp slabs -> per-row partial float4
    for (int r = t; r < rblk; r += NTHR) {
        int row = r_begin + r;
        if (row >= ROWS_T) break;
        int off = (r >> 3)*32 + ((r >> 2) & 1)*16 + (r & 3)*4;
        float den = 0.f, n0 = 0.f, n1 = 0.f, n2 = 0.f;
#pragma unroll
        for (int ww = 0; ww < 16; ww++) {
            const float* sp = &sPart[ww * (RBLK_MAX*4) + off];
            den += sp[0]; n0 += sp[1]; n1 += sp[2]; n2 += sp[3];
        }
        g_part[(size_t)ch * ROWS_T + row] = make_float4(den, n0, n1, n2);
    }
}

// ---------------- K3: combine halves, ELU, build x; init out=bias --------
__global__ void k_x(const float* __restrict__ bias, float* __restrict__ out) {
    int idx = blockIdx.x * blockDim.x + threadIdx.x;   // 16384
    if (idx < BATCH*100) out[idx] = bias[idx % 100];
    float4 A = g_part[idx];
    float4 B = g_part[ROWS_T + idx];
    float inv = 1.0f / (A.x + B.x);
    float x0 = (A.y + B.y) * inv;
    float x1 = (A.z + B.z) * inv;
    float x2 = (A.w + B.w) * inv;
    x0 = (x0 > 0.f) ? x0 : (expf(x0) - 1.f);
    x1 = (x1 > 0.f) ? x1 : (expf(x1) - 1.f);
    x2 = (x2 > 0.f) ? x2 : (expf(x2) - 1.f);
    float* xp = g_x + (size_t)idx * NHID;
    xp[0] = x0; xp[1] = x1; xp[2] = x2;
}

// ---------------- K4: out += x @ fc1_w.T  (split-K 12, high MLP) ---------
__global__ void k_fc(const float* __restrict__ w, float* __restrict__ out) {
    int o  = blockIdx.x;          // 0..99
    int kc = blockIdx.y;          // 0..11
    int t  = threadIdx.x;         // 128
    int wp = t >> 5, lane = t & 31;
    const int K4 = (N_ENT*NHID)/4;            // 3072 float4 per batch
    const float4* wr = (const float4*)(w + (size_t)o * (N_ENT*NHID));
    const float4* xv = (const float4*)g_x;
    int k0 = kc * 256 + t;

    float4 w0 = __ldg(wr + k0);
    float4 w1 = __ldg(wr + k0 + 128);
    float4 xa0 = xv[k0],          xa1 = xv[k0 + 128];
    float4 xb0 = xv[K4 + k0],     xb1 = xv[K4 + k0 + 128];
    float4 xc0 = xv[2*K4 + k0],   xc1 = xv[2*K4 + k0 + 128];
    float4 xd0 = xv[3*K4 + k0],   xd1 = xv[3*K4 + k0 + 128];

    float a0 = w0.x*xa0.x + w0.y*xa0.y + w0.z*xa0.z + w0.w*xa0.w
             + w1.x*xa1.x + w1.y*xa1.y + w1.z*xa1.z + w1.w*xa1.w;
    float a1 = w0.x*xb0.x + w0.y*xb0.y + w0.z*xb0.z + w0.w*xb0.w
             + w1.x*xb1.x + w1.y*xb1.y + w1.z*xb1.z + w1.w*xb1.w;
    float a2 = w0.x*xc0.x + w0.y*xc0.y + w0.z*xc0.z + w0.w*xc0.w
             + w1.x*xc1.x + w1.y*xc1.y + w1.z*xc1.z + w1.w*xc1.w;
    float a3 = w0.x*xd0.x + w0.y*xd0.y + w0.z*xd0.z + w0.w*xd0.w
             + w1.x*xd1.x + w1.y*xd1.y + w1.z*xd1.z + w1.w*xd1.w;

#pragma unroll
    for (int off = 16; off; off >>= 1) {
        a0 += __shfl_xor_sync(0xffffffffu, a0, off);
        a1 += __shfl_xor_sync(0xffffffffu, a1, off);
        a2 += __shfl_xor_sync(0xffffffffu, a2, off);
        a3 += __shfl_xor_sync(0xffffffffu, a3, off);
    }
    __shared__ float s4[4][4];
    if (lane == 0) {
        s4[0][wp] = a0; s4[1][wp] = a1; s4[2][wp] = a2; s4[3][wp] = a3;
    }
    __syncthreads();
    if (t < 4) {
        float r = s4[t][0] + s4[t][1] + s4[t][2] + s4[t][3];
        atomicAdd(&out[t*100 + o], r);
    }
}

// ---------------- launcher ----------------
extern "C" void kernel_launch(void* const* d_in, const int* in_sizes, int n_in,
                              void* d_out, int out_size) {
    const int*   adj  = (const int*)  d_in[0];
    const float* emb  = (const float*)d_in[1];
    const float* W    = (const float*)d_in[2];
    const float* a    = (const float*)d_in[3];
    const float* fc1w = (const float*)d_in[4];
    const float* fc1b = (const float*)d_in[5];
    float* out = (float*)d_out;

    static_assert(SMEM_MAIN <= 227*1024, "smem budget");
    cudaFuncSetAttribute(k_main, cudaFuncAttributeMaxDynamicSharedMemorySize,
                         SMEM_MAIN);

    k_node<<<N_ENT/256, 256>>>(emb, W, a);

    int sms = 148;
    int dev = 0;
    if (cudaGetDevice(&dev) == cudaSuccess) {
        int v = 0;
        if (cudaDeviceGetAttribute(&v, cudaDevAttrMultiProcessorCount, dev) == cudaSuccess && v > 0)
            sms = v;
    }
    k_main<<<2*sms, NTHR, SMEM_MAIN>>>(adj);

    k_x <<<ROWS_T/256, 256>>>(fc1b, out);
    k_fc<<<dim3(100, 12), 128>>>(fc1w, out);
}

// round 8
// speedup vs baseline: 1.6269x; 1.1009x over previous
#include <cuda_runtime.h>
#include <math.h>

#define N_ENT 4096
#define BATCH 4
#define NHID  3
#define ROWS_T (BATCH*N_ENT)     // 16384
#define RBLK_MAX 112             // rows per CTA (pad to 2)
#define NSTAGE 4
#define TILE_BYTES 32768         // 2 rows x 4096 ints x 4B
#define NTHR 512

// dynamic smem layout for k_main:
//   [0, 131072)        sAdj: 4 stages x 32KB
//   [131072, +1792)    sRow: RBLK_MAX float4
//   [132864, +28672)   sPart: 16 warps x RBLK_MAX x 4 floats
//   [161536, +128)     mbarriers: full[4] @ +0, empty[4] @ +64 (16B apart)
#define SROW_OFF   131072
#define SPART_OFF  (SROW_OFF + RBLK_MAX*16)
#define SMBAR_OFF  (SPART_OFF + 16*RBLK_MAX*4*4)
#define SMEM_MAIN  (SMBAR_OFF + 128)     // 161664 B

// ---------------- device scratch ----------------
__device__ float4  g_tabH[N_ENT];        // h0, h1, h2, dst
__device__ float   g_src[N_ENT];
__device__ unsigned g_dmax_u = 0;        // encoded float max (idempotent)
__device__ float   g_x[ROWS_T*NHID];

__device__ __forceinline__ unsigned fenc(float f) {
    unsigned u = __float_as_uint(f);
    return (u & 0x80000000u) ? ~u : (u | 0x80000000u);
}
__device__ __forceinline__ float fdec(unsigned e) {
    return (e & 0x80000000u) ? __uint_as_float(e & 0x7fffffffu)
                             : __uint_as_float(~e);
}
__device__ __forceinline__ void mbar_init(unsigned m, unsigned cnt) {
    asm volatile("mbarrier.init.shared.b64 [%0], %1;" :: "r"(m), "r"(cnt) : "memory");
}
__device__ __forceinline__ void mbar_expect_tx(unsigned m, unsigned bytes) {
    asm volatile("mbarrier.arrive.expect_tx.shared.b64 _, [%0], %1;"
                 :: "r"(m), "r"(bytes) : "memory");
}
__device__ __forceinline__ void mbar_arrive(unsigned m) {
    asm volatile("mbarrier.arrive.shared.b64 _, [%0];" :: "r"(m) : "memory");
}
__device__ __forceinline__ void mbar_wait(unsigned m, unsigned phase) {
    asm volatile(
        "{\n\t.reg .pred P;\n"
        "W_%=:\n\t"
        "mbarrier.try_wait.parity.acquire.cta.shared::cta.b64 P, [%0], %1, 0x989680;\n\t"
        "@!P bra W_%=;\n\t}"
        :: "r"(m), "r"(phase) : "memory");
}
__device__ __forceinline__ void bulk_cp(unsigned dst, const void* src,
                                        unsigned bytes, unsigned m) {
    asm volatile(
        "cp.async.bulk.shared::cta.global.mbarrier::complete_tx::bytes "
        "[%0], [%1], %2, [%3];"
        :: "r"(dst), "l"(src), "r"(bytes), "r"(m) : "memory");
}

// ---------------- K1: h = emb@W, src/dst per node, atomic dstmax ----------
__global__ void k_node(const float* __restrict__ emb,
                       const float* __restrict__ W,
                       const float* __restrict__ a) {
    __shared__ float sW[192];
    __shared__ float sa[6];
    __shared__ float sm[256];
    int t = threadIdx.x;
    if (t < 192) sW[t] = W[t];
    if (t < 6)   sa[t] = a[t];
    __syncthreads();

    int i = blockIdx.x * blockDim.x + t;
    const float4* ev = (const float4*)(emb + (size_t)i * 64);
    float h0 = 0.f, h1 = 0.f, h2 = 0.f;
#pragma unroll
    for (int k4 = 0; k4 < 16; k4++) {
        float4 e = ev[k4];
        int k = k4 * 4;
        h0 += e.x*sW[k*3+0] + e.y*sW[k*3+3] + e.z*sW[k*3+6] + e.w*sW[k*3+9];
        h1 += e.x*sW[k*3+1] + e.y*sW[k*3+4] + e.z*sW[k*3+7] + e.w*sW[k*3+10];
        h2 += e.x*sW[k*3+2] + e.y*sW[k*3+5] + e.z*sW[k*3+8] + e.w*sW[k*3+11];
    }
    float src = h0*sa[0] + h1*sa[1] + h2*sa[2];
    float dst = h0*sa[3] + h1*sa[4] + h2*sa[5];
    g_tabH[i] = make_float4(h0, h1, h2, dst);
    g_src[i]  = src;

    sm[t] = dst;
    __syncthreads();
    for (int s = 128; s > 0; s >>= 1) {
        if (t < s) sm[t] = fmaxf(sm[t], sm[t+s]);
        __syncthreads();
    }
    if (t == 0) atomicMax(&g_dmax_u, fenc(sm[0]));
}

// ---------------- K2: main pass — single-wave mbarrier ring ---------------
// Grid = 148 (1 CTA/SM, 1 wave), 512 threads. CTA owns full 4096-col rows.
// Warp w owns cols [w*256, w*256+256); lane owns 8 (tables in regs).
// Tile = 2 adjacent rows = one 32KB bulk copy; 4-stage ring; empty barriers
// (512 arrivals) recycle stages — no __syncthreads in the loop. Epilogue
// computes final x = ELU(num/den) directly.
__global__ void __launch_bounds__(NTHR, 1) k_main(const int* __restrict__ adj) {
    extern __shared__ char dsm[];
    float4* sRow  = (float4*)(dsm + SROW_OFF);
    float*  sPart = (float*)(dsm + SPART_OFF);
    unsigned sb   = (unsigned)__cvta_generic_to_shared(dsm);
    unsigned mb_full  = sb + SMBAR_OFF;        // full[s]  @ +16*s
    unsigned mb_empty = sb + SMBAR_OFF + 64;   // empty[s] @ +16*s

    int t = threadIdx.x, w = t >> 5, lane = t & 31;
    int j0 = w * 256 + lane * 8;

    float dm = fdec(g_dmax_u);

    // per-lane column tables (register-resident)
    float p[8], q[8], h0[8], h1[8], h2[8];
#pragma unroll
    for (int k = 0; k < 8; k++) {
        float4 H = g_tabH[j0 + k];
        h0[k] = H.x; h1[k] = H.y; h2[k] = H.z;
        float d = H.w - dm;
        p[k] = expf(d);
        q[k] = expf(0.2f * d);
    }

    int G = gridDim.x;
    int rblk = (((ROWS_T + G - 1) / G) + 1) & ~1;    // mult of 2
    if (rblk > RBLK_MAX) rblk = RBLK_MAX;
    int r_begin = blockIdx.x * rblk;
    int iters = rblk >> 1;                            // 2 rows per tile

    // per-row constants u, v, w0
    for (int r = t; r < rblk; r += NTHR) {
        int row = min(r_begin + r, ROWS_T - 1);
        float src = g_src[row & (N_ENT - 1)];
        float z  = src + dm;
        float lz = fmaxf(z, 0.2f * z);
        float m  = fmaxf(lz, 9e-15f);
        sRow[r] = make_float4(expf(z - m), expf(0.2f*z - m),
                              expf(9e-15f - m), 0.f);
    }

    if (t == 0) {
#pragma unroll
        for (int s = 0; s < NSTAGE; s++) {
            mbar_init(mb_full  + 16*s, 1);
            mbar_init(mb_empty + 16*s, NTHR);
        }
    }
    __syncthreads();
    asm volatile("fence.proxy.async.shared::cta;" ::: "memory");

    // producer: one 32KB bulk copy per tile (rows adjacent in memory)
    auto issue = [&](int j) {
        int s = j & (NSTAGE - 1);
        unsigned m = mb_full + 16*s;
        mbar_expect_tx(m, TILE_BYTES);
        int rr = min(r_begin + j*2, ROWS_T - 2);
        bulk_cp(sb + (unsigned)(s * TILE_BYTES),
                adj + ((size_t)rr << 12), TILE_BYTES, m);
    };

    if (t == 0)
        for (int j = 0; j < NSTAGE && j < iters; j++) issue(j);

    int myoff = w * 1024 + lane * 32;     // byte offset of lane's 8 cols in a row

    for (int it = 0; it < iters; it++) {
        int s = it & (NSTAGE - 1);
        mbar_wait(mb_full + 16*s, (it >> 2) & 1);

        const char* sT = dsm + s * TILE_BYTES;

        float v[8];
#pragma unroll
        for (int r = 0; r < 2; r++) {
            float4 rc = sRow[it*2 + r];        // u, v, w0 (broadcast)
            int4 A = *(const int4*)(sT + r*16384 + myoff);
            int4 B = *(const int4*)(sT + r*16384 + myoff + 16);
            int va[8];
            *(int4*)&va[0] = A;
            *(int4*)&va[4] = B;
            float a0 = 0.f, a1 = 0.f, a2 = 0.f, a3 = 0.f;
#pragma unroll
            for (int k = 0; k < 8; k++) {
                float we = fmaxf(rc.x * p[k], rc.y * q[k]);
                float c  = (va[k] > 0) ? we : rc.z;
                a0 += c;
                a1 += c * h0[k];
                a2 += c * h1[k];
                a3 += c * h2[k];
            }
            v[r*4+0] = a0; v[r*4+1] = a1; v[r*4+2] = a2; v[r*4+3] = a3;
        }

        // done reading stage s
        mbar_arrive(mb_empty + 16*s);

        // butterfly transpose-reduce (8 values): lane i<8 -> warp total of v[i]
#pragma unroll
        for (int d = 4; d >= 1; d >>= 1) {
            int bit = (lane & d) ? 1 : 0;
#pragma unroll
            for (int k = 0; k < d; k++) {
                float snd = bit ? v[k] : v[k+d];
                float tmp = __shfl_xor_sync(0xffffffffu, snd, d);
                v[k] = (bit ? v[k+d] : v[k]) + tmp;
            }
        }
        v[0] += __shfl_xor_sync(0xffffffffu, v[0], 8);
        v[0] += __shfl_xor_sync(0xffffffffu, v[0], 16);

        if (lane < 8)
            sPart[w * (RBLK_MAX*4) + it*8 + lane] = v[0];

        // producer refills this stage 4 tiles ahead
        if (t == 0) {
            int j = it + NSTAGE;
            if (j < iters) {
                mbar_wait(mb_empty + 16*s, (it >> 2) & 1);
                issue(j);
            }
        }
    }

    __syncthreads();

    // epilogue: combine 16 warp slabs -> x = ELU(num/den)
    for (int r = t; r < rblk; r += NTHR) {
        int row = r_begin + r;
        if (row >= ROWS_T) break;
        float den = 0.f, n0 = 0.f, n1 = 0.f, n2 = 0.f;
#pragma unroll
        for (int ww = 0; ww < 16; ww++) {
            const float* sp = &sPart[ww * (RBLK_MAX*4) + r*4];
            den += sp[0]; n0 += sp[1]; n1 += sp[2]; n2 += sp[3];
        }
        float inv = 1.0f / den;
        float x0 = n0 * inv, x1 = n1 * inv, x2 = n2 * inv;
        x0 = (x0 > 0.f) ? x0 : (expf(x0) - 1.f);
        x1 = (x1 > 0.f) ? x1 : (expf(x1) - 1.f);
        x2 = (x2 > 0.f) ? x2 : (expf(x2) - 1.f);
        float* xp = g_x + (size_t)row * NHID;
        xp[0] = x0; xp[1] = x1; xp[2] = x2;
    }
}

// ---------------- K3: out = x @ fc1_w.T + b  (one dot per block) ---------
__global__ void k_fc(const float* __restrict__ w,
                     const float* __restrict__ bias,
                     float* __restrict__ out) {
    int o = blockIdx.x;          // 0..99
    int b = blockIdx.y;          // 0..3
    int t = threadIdx.x;         // 256
    int wp = t >> 5, lane = t & 31;
    const float4* wr = (const float4*)(w + (size_t)o * (N_ENT*NHID));
    const float4* xv = (const float4*)g_x + b * ((N_ENT*NHID)/4);

    float a0 = 0.f, a1 = 0.f, a2 = 0.f, a3 = 0.f;
#pragma unroll
    for (int i = 0; i < 12; i++) {
        int k = t + i * 256;
        float4 wv = __ldg(wr + k);
        float4 xx = xv[k];
        float s = wv.x*xx.x + wv.y*xx.y + wv.z*xx.z + wv.w*xx.w;
        if ((i & 3) == 0) a0 += s;
        else if ((i & 3) == 1) a1 += s;
        else if ((i & 3) == 2) a2 += s;
        else a3 += s;
    }
    float acc = (a0 + a1) + (a2 + a3);
#pragma unroll
    for (int off = 16; off; off >>= 1)
        acc += __shfl_xor_sync(0xffffffffu, acc, off);

    __shared__ float sw[8];
    if (lane == 0) sw[wp] = acc;
    __syncthreads();
    if (t == 0) {
        float s = 0.f;
#pragma unroll
        for (int i = 0; i < 8; i++) s += sw[i];
        out[b*100 + o] = s + bias[o];
    }
}

// ---------------- launcher ----------------
extern "C" void kernel_launch(void* const* d_in, const int* in_sizes, int n_in,
                              void* d_out, int out_size) {
    const int*   adj  = (const int*)  d_in[0];
    const float* emb  = (const float*)d_in[1];
    const float* W    = (const float*)d_in[2];
    const float* a    = (const float*)d_in[3];
    const float* fc1w = (const float*)d_in[4];
    const float* fc1b = (const float*)d_in[5];
    float* out = (float*)d_out;

    static_assert(SMEM_MAIN <= 227*1024, "smem budget");
    cudaFuncSetAttribute(k_main, cudaFuncAttributeMaxDynamicSharedMemorySize,
                         SMEM_MAIN);

    k_node<<<N_ENT/256, 256>>>(emb, W, a);

    int sms = 148;
    int dev = 0;
    if (cudaGetDevice(&dev) == cudaSuccess) {
        int v = 0;
        if (cudaDeviceGetAttribute(&v, cudaDevAttrMultiProcessorCount, dev) == cudaSuccess && v > 0)
            sms = v;
    }
    k_main<<<sms, NTHR, SMEM_MAIN>>>(adj);

    k_fc<<<dim3(100, BATCH), 256>>>(fc1w, fc1b, out);
}